// round 15
// baseline (speedup 1.0000x reference)
#include <cuda_runtime.h>
#include <cuda.h>
#include <cstdint>

#define TOKENS 4096
#define HIDDEN 4096
#define INTER  14336

// tf32 truncation-bias compensation: HW fp32->tf32 truncates mantissa toward
// zero; mean relative shrink per operand ~= 3.4e-4, coherent with the output.
// GEMM1 feeds BOTH operands raw (x and w_gate_up) -> compensate twice.
#define COMP2 1.00068f

#if defined(__CUDA_ARCH__) && (defined(__CUDA_ARCH_FEAT_SM103_ALL) || \
                               defined(__CUDA_ARCH_FEAT_SM100_ALL) || \
                               defined(__CUDA_ARCH_FEAT_SM101_ALL))
#define TCGEN_OK 1
#else
#define TCGEN_OK 0
#endif

// ------------------------- device scratch -----------------------------------
__device__ float g_wdr[(size_t)HIDDEN * INTER];    // 224 MB rounded w_down
__device__ float g_h2[(size_t)TOKENS * INTER];     // 224 MB intermediate
// split-K handoff flags, one per (mb,nb,rank) tile-half. Zero-initialized at
// load; kh0 epilogue sets to 1 (release), kh1 epilogue consumes and resets to
// 0, so every graph replay starts clean without a prep kernel.
__device__ uint32_t g_kflag[512];

// ------------------------- PTX helpers --------------------------------------
__device__ __forceinline__ uint32_t smem_u32(const void* p) {
    uint32_t a;
    asm("{ .reg .u64 t; cvta.to.shared.u64 t, %1; cvt.u32.u64 %0, t; }"
        : "=r"(a) : "l"(p));
    return a;
}

#if TCGEN_OK
__device__ __forceinline__ uint32_t ctarank() {
    uint32_t r;
    asm("mov.u32 %0, %%cluster_ctarank;" : "=r"(r));
    return r;
}
__device__ __forceinline__ void mbar_init(uint32_t a, uint32_t c) {
    asm volatile("mbarrier.init.shared.b64 [%0], %1;" :: "r"(a), "r"(c) : "memory");
}
__device__ __forceinline__ void mbar_expect_tx(uint32_t a, uint32_t bytes) {
    asm volatile("mbarrier.arrive.expect_tx.shared.b64 _, [%0], %1;"
                 :: "r"(a), "r"(bytes) : "memory");
}
__device__ __forceinline__ void mbar_arrive_leader(uint32_t a) {
    asm volatile(
        "{\n\t.reg .b32 r;\n\t"
        "and.b32 r, %0, 0xFEFFFFFF;\n\t"
        "mbarrier.arrive.shared::cluster.b64 _, [r];\n\t}"
        :: "r"(a) : "memory");
}
__device__ __forceinline__ void mbar_wait(uint32_t a, uint32_t parity) {
    asm volatile(
        "{\n\t"
        ".reg .pred P;\n"
        "LAB_%=:\n\t"
        "mbarrier.try_wait.parity.acquire.cta.shared::cta.b64 P, [%0], %1, 0x989680;\n\t"
        "@P bra DONE_%=;\n\t"
        "bra LAB_%=;\n"
        "DONE_%=:\n\t"
        "}"
        :: "r"(a), "r"(parity) : "memory");
}
__device__ __forceinline__ void tcg_commit_mc2(uint32_t a) {
    asm volatile(
        "tcgen05.commit.cta_group::2.mbarrier::arrive::one.shared::cluster."
        "multicast::cluster.b64 [%0], %1;"
        :: "r"(a), "h"((uint16_t)0x3) : "memory");
}
__device__ __forceinline__ void tma2d_cg2(uint32_t dst, const CUtensorMap* m,
                                          int cx, int cy, uint32_t bar) {
    asm volatile(
        "{\n\t.reg .b32 lb;\n\t"
        "and.b32 lb, %4, 0xFEFFFFFF;\n\t"
        "cp.async.bulk.tensor.2d.cta_group::2.shared::cluster.global.tile."
        "mbarrier::complete_tx::bytes [%0], [%1, {%2, %3}], [lb];\n\t}"
        :: "r"(dst), "l"(m), "r"(cx), "r"(cy), "r"(bar) : "memory");
}
#define TC_ALLOC_CG2(dstsmem, n) \
    asm volatile("tcgen05.alloc.cta_group::2.sync.aligned.shared::cta.b32 [%0], %1;" \
                 :: "r"(dstsmem), "r"(n) : "memory")
#define TC_DEALLOC_CG2(t, n) \
    asm volatile("tcgen05.dealloc.cta_group::2.sync.aligned.b32 %0, %1;" :: "r"(t), "r"(n))
#define TC_RELINQ_CG2() \
    asm volatile("tcgen05.relinquish_alloc_permit.cta_group::2.sync.aligned;")
#define TC_FENCE_AFTER()  asm volatile("tcgen05.fence::after_thread_sync;" ::: "memory")
#define TC_FENCE_BEFORE() asm volatile("tcgen05.fence::before_thread_sync;" ::: "memory")
#define TC_WAIT_LD()      asm volatile("tcgen05.wait::ld.sync.aligned;" ::: "memory")
#define CLUSTER_ARRIVE()  asm volatile("barrier.cluster.arrive.aligned;" ::: "memory")
#define CLUSTER_WAIT()    asm volatile("barrier.cluster.wait.aligned;" ::: "memory")

__device__ __forceinline__ void mma_tf32_ss_cg2(uint32_t d_tmem, uint64_t ad, uint64_t bd,
                                                uint32_t idesc, uint32_t en) {
    asm volatile(
        "{\n\t"
        ".reg .pred p;\n\t"
        "setp.ne.u32 p, %5, 0;\n\t"
        "tcgen05.mma.cta_group::2.kind::tf32 [%0], %1, %2, %3, "
        "{%4, %4, %4, %4, %4, %4, %4, %4}, p;\n\t"
        "}"
        :: "r"(d_tmem), "l"(ad), "l"(bd), "r"(idesc), "r"(0u), "r"(en) : "memory");
}

__device__ __forceinline__ uint64_t make_desc(uint32_t addr) {
    return ((uint64_t)2 << 61) | ((uint64_t)1 << 46) | ((uint64_t)64 << 32) |
           ((uint64_t)1 << 16) | ((uint64_t)(addr >> 4) & 0x3FFF);
}

__device__ __forceinline__ void ldtm32(uint32_t* r, uint32_t addr) {
    asm volatile(
        "tcgen05.ld.sync.aligned.32x32b.x32.b32 "
        "{%0, %1, %2, %3, %4, %5, %6, %7, "
        " %8, %9, %10, %11, %12, %13, %14, %15, "
        " %16, %17, %18, %19, %20, %21, %22, %23, "
        " %24, %25, %26, %27, %28, %29, %30, %31}, [%32];"
        : "=r"(r[0]),  "=r"(r[1]),  "=r"(r[2]),  "=r"(r[3]),
          "=r"(r[4]),  "=r"(r[5]),  "=r"(r[6]),  "=r"(r[7]),
          "=r"(r[8]),  "=r"(r[9]),  "=r"(r[10]), "=r"(r[11]),
          "=r"(r[12]), "=r"(r[13]), "=r"(r[14]), "=r"(r[15]),
          "=r"(r[16]), "=r"(r[17]), "=r"(r[18]), "=r"(r[19]),
          "=r"(r[20]), "=r"(r[21]), "=r"(r[22]), "=r"(r[23]),
          "=r"(r[24]), "=r"(r[25]), "=r"(r[26]), "=r"(r[27]),
          "=r"(r[28]), "=r"(r[29]), "=r"(r[30]), "=r"(r[31])
        : "r"(addr));
}

__device__ __forceinline__ void spin_eq(const uint32_t* p, uint32_t want) {
    while (true) {
        uint32_t v;
        asm volatile("ld.acquire.gpu.global.u32 %0, [%1];" : "=r"(v) : "l"(p));
        if (v == want) break;
        __nanosleep(64);
    }
}
__device__ __forceinline__ void st_release_u32(uint32_t* p, uint32_t v) {
    asm volatile("st.release.gpu.global.u32 [%0], %1;" :: "l"(p), "r"(v) : "memory");
}
__device__ __forceinline__ void st_relaxed_u32(uint32_t* p, uint32_t v) {
    asm volatile("st.relaxed.gpu.global.u32 [%0], %1;" :: "l"(p), "r"(v) : "memory");
}
#endif  // TCGEN_OK

__device__ __forceinline__ float rna_tf32(float v) {
    uint32_t r;
    asm("cvt.rna.tf32.f32 %0, %1;" : "=r"(r) : "f"(v));
    return __uint_as_float(r);
}
// gate/up carry x AND w_gate_up truncation shrink: compensate each by COMP2,
// then silu(gate)*up, then rna-round for the next tf32 GEMM.
__device__ __forceinline__ float silu_mul_comp(uint32_t gb, uint32_t ub) {
    float g = __uint_as_float(gb) * COMP2;
    float u = __uint_as_float(ub) * COMP2;
    float s = g / (1.0f + __expf(-g));
    return rna_tf32(s * u);
}

__device__ __forceinline__ float4 ldg_nc4(const float4* p) {
    float4 v;
    asm volatile("ld.global.nc.v4.f32 {%0,%1,%2,%3}, [%4];"
                 : "=f"(v.x), "=f"(v.y), "=f"(v.z), "=f"(v.w) : "l"(p));
    return v;
}
__device__ __forceinline__ void stg_cs4(float4* p, float4 v) {
    asm volatile("st.global.cs.v4.f32 [%0], {%1,%2,%3,%4};"
                 :: "l"(p), "f"(v.x), "f"(v.y), "f"(v.z), "f"(v.w) : "memory");
}
__device__ __forceinline__ float4 rna4(float4 v) {
    v.x = rna_tf32(v.x);
    v.y = rna_tf32(v.y);
    v.z = rna_tf32(v.z);
    v.w = rna_tf32(v.w);
    return v;
}

// ------------------------- persistent 2CTA tf32 tcgen05 GEMM ----------------
// Cluster(2): tile M=256 (128 rows/CTA), N=256 (B split N/2=128 rows/CTA).
// FUSED (GEMM1): raw x + raw w_gate_up via TMA (COMP2 in epilogue); rank0's
//   B rows = gate block, rank1's = up block; warps 6-7 stream-round
//   w_down -> g_wdr under GEMM1's spare DRAM bandwidth.
// GEMM2: split-K=2, 512 tickets of 224 K-steps. kh=0 stores out; kh=1 does an
//   IN-PLACE combine (out += partial). Ordering: ticket striping guarantees
//   kh1 of tile idx runs >= 3 slots (~195us) after kh0, so the per-tile-half
//   release/acquire flag is set long before kh1's epilogue polls it. kh1
//   resets the flag -> graph replays start clean with no prep kernel.
#define STAGES      6
#define STAGE_BYTES 32768
#define OFF_FULL    8
#define OFF_EMPTY   (OFF_FULL  + 8 * STAGES)
#define OFF_MMAD    (OFF_EMPTY + 8 * STAGES)
#define OFF_EPID    (OFF_MMAD + 16)
#define OFF_STAGE   1024
#define SMEM_TOTAL  (OFF_STAGE + STAGES * STAGE_BYTES)   /* 197632 */
#define STAGE_TX    65536
#define KSPLIT      (INTER / 2)                           /* 7168 */

static constexpr uint32_t IDESC_CG2 =
    (1u << 4) | (2u << 7) | (2u << 10) | ((256u / 8) << 17) | ((256u / 16) << 24);

template <bool FUSED>
__global__ void __launch_bounds__(256, 1) __cluster_dims__(2, 1, 1)
gemm_tf32_kernel(const __grid_constant__ CUtensorMap tma_a,
                 const __grid_constant__ CUtensorMap tma_b,
                 float* __restrict__ out,
                 const float4* __restrict__ rsrc,   // raw w_down (FUSED only)
                 float4* __restrict__ rdst,         // g_wdr      (FUSED only)
                 int rn4) {
#if TCGEN_OK
    constexpr int MB_TILES = 16;                            // 4096 / 256
    constexpr int NK    = FUSED ? (HIDDEN / 32) : (KSPLIT / 32);  // 128 / 224
    constexpr int TOTAL = FUSED ? 1792 : 512;               // tiles / tickets

    extern __shared__ char smem[];
    const uint32_t sb = smem_u32(smem);
    const int tid  = threadIdx.x;
    const int wid  = tid >> 5;
    const int lane = tid & 31;
    const uint32_t rank = ctarank();
    const int cid  = blockIdx.x >> 1;
    const int ncl  = gridDim.x >> 1;
    const int my_tiles = (TOTAL - cid + ncl - 1) / ncl;

    if (tid == 0) {
#pragma unroll
        for (int s = 0; s < STAGES; s++) {
            mbar_init(sb + OFF_FULL  + s * 8, 1);
            mbar_init(sb + OFF_EMPTY + s * 8, 1);
        }
        mbar_init(sb + OFF_MMAD,     1);
        mbar_init(sb + OFF_MMAD + 8, 1);
        mbar_init(sb + OFF_EPID,     256);
        mbar_init(sb + OFF_EPID + 8, 256);
    }
    __syncthreads();
    if (wid == 0) TC_ALLOC_CG2(sb, 512);
    __syncthreads();
    uint32_t tmem;
    asm volatile("ld.shared.b32 %0, [%1];" : "=r"(tmem) : "r"(sb));

    CLUSTER_ARRIVE();
    CLUSTER_WAIT();

    if (wid == 4 && lane == 0) {
        // ---------------- TMA producer (both CTAs) --------------------------
        int st = 0, sph = 1;
        for (int i = 0; i < my_tiles; i++) {
            const int t  = cid + i * ncl;
            const int r_ = FUSED ? t : (t & 255);
            const int mb = r_ % MB_TILES;
            const int nb = r_ / MB_TILES;
            const int kc0 = FUSED ? 0 : ((t >> 8) * KSPLIT);
            const int a_row = mb * 256 + (int)rank * 128;
            const int b_row = FUSED ? (nb * 128 + (int)rank * INTER)
                                    : (nb * 256 + (int)rank * 128);
            for (int ks = 0; ks < NK; ks++) {
                mbar_wait(sb + OFF_EMPTY + st * 8, (uint32_t)sph);
                const uint32_t bar = sb + OFF_FULL + st * 8;
                if (rank == 0) mbar_expect_tx(bar, STAGE_TX);
                const int kc = kc0 + ks * 32;
                const uint32_t base = sb + OFF_STAGE + st * STAGE_BYTES;
                tma2d_cg2(base,         &tma_a, kc, a_row, bar);
                tma2d_cg2(base + 16384, &tma_b, kc, b_row, bar);
                if (++st == STAGES) { st = 0; sph ^= 1; }
            }
        }
    } else if (rank == 0 && wid == 5 && lane == 0) {
        // ---------------- MMA issuer (leader only) --------------------------
        int st = 0, fph = 0;
        int e0 = 1, e1 = 1;
        for (int i = 0; i < my_tiles; i++) {
            const int b = i & 1;
            mbar_wait(sb + OFF_EPID + b * 8, (uint32_t)(b ? e1 : e0));
            if (b) e1 ^= 1; else e0 ^= 1;
            TC_FENCE_AFTER();
            const uint32_t dtm = tmem + b * 256;
            uint32_t en = 0;
            for (int ks = 0; ks < NK; ks++) {
                mbar_wait(sb + OFF_FULL + st * 8, (uint32_t)fph);
                const uint32_t base = sb + OFF_STAGE + st * STAGE_BYTES;
                const uint64_t ad = make_desc(base);
                const uint64_t bd = make_desc(base + 16384);
#pragma unroll
                for (int j = 0; j < 4; j++) {
                    mma_tf32_ss_cg2(dtm, ad + j * 2, bd + j * 2, IDESC_CG2, en);
                    en = 1;
                }
                tcg_commit_mc2(sb + OFF_EMPTY + st * 8);
                if (++st == STAGES) { st = 0; fph ^= 1; }
            }
            tcg_commit_mc2(sb + OFF_MMAD + b * 8);
        }
    } else if (FUSED && wid >= 6) {
        // -------- side crew (FUSED only): stream-round w_down -> g_wdr -----
        const int nthr = gridDim.x * 64;
        for (int i = blockIdx.x * 64 + (tid - 192); i < rn4; i += nthr) {
            stg_cs4(rdst + i, rna4(ldg_nc4(rsrc + i)));
        }
    } else if (tid < 128) {
        // ---------------- epilogue (both CTAs, own 128 rows) -----------------
        int m0 = 0, m1 = 0;
        for (int i = 0; i < my_tiles; i++) {
            const int t  = cid + i * ncl;
            const int r_ = FUSED ? t : (t & 255);
            const int mb = r_ % MB_TILES;
            const int nb = r_ / MB_TILES;
            const int b  = i & 1;
            mbar_wait(sb + OFF_MMAD + b * 8, (uint32_t)(b ? m1 : m0));
            if (b) m1 ^= 1; else m0 ^= 1;
            TC_FENCE_AFTER();
            const uint32_t buf = tmem + b * 256;
            const int row = mb * 256 + (int)rank * 128 + tid;
            if (FUSED) {
                float* dst = out + (size_t)row * INTER + (size_t)nb * 128;
#pragma unroll
                for (int c0 = 0; c0 < 128; c0 += 32) {
                    uint32_t ga[32], ua[32];
                    ldtm32(ga, buf + c0);          // gate: D cols 0-127
                    ldtm32(ua, buf + 128 + c0);    // up:   D cols 128-255
                    TC_WAIT_LD();
#pragma unroll
                    for (int q = 0; q < 8; q++) {
                        float4 v;
                        v.x = silu_mul_comp(ga[q * 4 + 0], ua[q * 4 + 0]);
                        v.y = silu_mul_comp(ga[q * 4 + 1], ua[q * 4 + 1]);
                        v.z = silu_mul_comp(ga[q * 4 + 2], ua[q * 4 + 2]);
                        v.w = silu_mul_comp(ga[q * 4 + 3], ua[q * 4 + 3]);
                        *reinterpret_cast<float4*>(dst + c0 + q * 4) = v;
                    }
                }
                TC_FENCE_BEFORE();
                mbar_arrive_leader(sb + OFF_EPID + b * 8);
            } else {
                const int kh   = t >> 8;
                const int fidx = ((mb * 16 + nb) << 1) + (int)rank;
                float* dst = out + (size_t)row * HIDDEN + (size_t)nb * 256;
                if (kh) {
                    // kh0 of this tile-half ran >= 3 slots (~195us) ago;
                    // acquire makes its stores visible. Poll succeeds at once.
                    spin_eq(&g_kflag[fidx], 1u);
                }
#pragma unroll
                for (int c0 = 0; c0 < 256; c0 += 32) {
                    uint32_t da[32];
                    ldtm32(da, buf + c0);
                    TC_WAIT_LD();
#pragma unroll
                    for (int q = 0; q < 8; q++) {
                        float4 v;   // h2 and w_down both rna-rounded: no COMP
                        v.x = __uint_as_float(da[q * 4 + 0]);
                        v.y = __uint_as_float(da[q * 4 + 1]);
                        v.z = __uint_as_float(da[q * 4 + 2]);
                        v.w = __uint_as_float(da[q * 4 + 3]);
                        float4* p = reinterpret_cast<float4*>(dst + c0 + q * 4);
                        if (kh) {   // in-place split-K combine
                            float4 o = *p;
                            v.x += o.x; v.y += o.y; v.z += o.z; v.w += o.w;
                        }
                        *p = v;
                    }
                }
                TC_FENCE_BEFORE();
                mbar_arrive_leader(sb + OFF_EPID + b * 8);
                // flag handoff (off the MMA critical path, after EPID arrive)
                asm volatile("bar.sync 1, 128;" ::: "memory");
                if (tid == 0) {
                    if (kh) st_relaxed_u32(&g_kflag[fidx], 0u);  // replay reset
                    else    st_release_u32(&g_kflag[fidx], 1u);  // publish kh0
                }
            }
        }
    }
    __syncthreads();
    CLUSTER_ARRIVE();
    CLUSTER_WAIT();
    if (wid == 0) {
        TC_RELINQ_CG2();
        TC_DEALLOC_CG2(tmem, 512);
    }
    CLUSTER_ARRIVE();
    CLUSTER_WAIT();
#endif  // TCGEN_OK
}

// ------------------------- host side ----------------------------------------
typedef CUresult (*PFN_encode)(CUtensorMap*, CUtensorMapDataType, cuuint32_t, void*,
                               const cuuint64_t*, const cuuint64_t*, const cuuint32_t*,
                               const cuuint32_t*, CUtensorMapInterleave, CUtensorMapSwizzle,
                               CUtensorMapL2promotion, CUtensorMapFloatOOBfill);

static PFN_encode get_encode_fn() {
    static void* fn = nullptr;
    if (!fn) {
        cudaDriverEntryPointQueryResult qr;
#if CUDART_VERSION >= 12050
        cudaGetDriverEntryPointByVersion("cuTensorMapEncodeTiled", &fn, 12000,
                                         cudaEnableDefault, &qr);
#else
        cudaGetDriverEntryPoint("cuTensorMapEncodeTiled", &fn, cudaEnableDefault, &qr);
#endif
    }
    return (PFN_encode)fn;
}

static void make_map(CUtensorMap* tm, void* base, uint64_t d0, uint64_t d1) {
    PFN_encode enc = get_encode_fn();
    cuuint64_t dims[2]    = {d0, d1};
    cuuint64_t strides[1] = {d0 * 4};
    cuuint32_t box[2]     = {32, 128};
    cuuint32_t es[2]      = {1, 1};
    enc(tm, CU_TENSOR_MAP_DATA_TYPE_FLOAT32, 2, base, dims, strides, box, es,
        CU_TENSOR_MAP_INTERLEAVE_NONE, CU_TENSOR_MAP_SWIZZLE_128B,
        CU_TENSOR_MAP_L2_PROMOTION_L2_128B, CU_TENSOR_MAP_FLOAT_OOB_FILL_NONE);
}

extern "C" void kernel_launch(void* const* d_in, const int* in_sizes, int n_in,
                              void* d_out, int out_size) {
    const float* x   = (const float*)d_in[0];
    const float* wgu = (const float*)d_in[1];
    const float* wd  = (const float*)d_in[2];
    float* out = (float*)d_out;

    float *p_wdr, *p_h2;
    cudaGetSymbolAddress((void**)&p_wdr, g_wdr);
    cudaGetSymbolAddress((void**)&p_h2,  g_h2);

    CUtensorMap tmA1, tmB1, tmA2, tmB2;
    make_map(&tmA1, (void*)x,    HIDDEN, TOKENS);               // raw x
    make_map(&tmB1, (void*)wgu,  HIDDEN, 2 * (uint64_t)INTER);  // raw weights
    make_map(&tmA2, p_h2,        INTER,  TOKENS);
    make_map(&tmB2, p_wdr,       INTER,  HIDDEN);   // rounded inside GEMM1

    cudaFuncSetAttribute(gemm_tf32_kernel<true>,
                         cudaFuncAttributeMaxDynamicSharedMemorySize, SMEM_TOTAL);
    cudaFuncSetAttribute(gemm_tf32_kernel<false>,
                         cudaFuncAttributeMaxDynamicSharedMemorySize, SMEM_TOTAL);

    int dev = 0;
    cudaGetDevice(&dev);
    int nsm = 148;
    cudaDeviceGetAttribute(&nsm, cudaDevAttrMultiProcessorCount, dev);
    nsm &= ~1;   // multiple of cluster size (2)

    // No prep kernel: x and wgu go in raw (COMP2 in GEMM1 epilogue);
    // wd is rounded by GEMM1's side warps; h2 is rna-rounded at source;
    // split-K flags self-reset inside GEMM2.

    // GEMM1: h2 = silu(x@Wg^T) * (x@Wu^T), persistent 2CTA clusters.
    // Warps 6-7 stream-round w_down -> g_wdr in the background.
    gemm_tf32_kernel<true><<<nsm, 256, SMEM_TOTAL>>>(
        tmA1, tmB1, p_h2, (const float4*)wd, (float4*)p_wdr,
        (int)((size_t)HIDDEN * INTER / 4));

    // GEMM2: out = h2 @ Wd^T, split-K=2 with ordered in-place combine
    // (kh0 stores, kh1 adds; no partial buffer, no reduce kernel).
    gemm_tf32_kernel<false><<<nsm, 192, SMEM_TOTAL>>>(
        tmA2, tmB2, out, nullptr, nullptr, 0);
}

// round 16
// speedup vs baseline: 1.0161x; 1.0161x over previous
#include <cuda_runtime.h>
#include <cuda.h>
#include <cstdint>

#define TOKENS 4096
#define HIDDEN 4096
#define INTER  14336

// tf32 truncation-bias compensation: HW fp32->tf32 truncates mantissa toward
// zero; mean relative shrink per operand ~= 3.4e-4, coherent with the output.
// GEMM1 feeds BOTH operands raw (x and w_gate_up) -> compensate twice.
#define COMP2 1.00068f

#if defined(__CUDA_ARCH__) && (defined(__CUDA_ARCH_FEAT_SM103_ALL) || \
                               defined(__CUDA_ARCH_FEAT_SM100_ALL) || \
                               defined(__CUDA_ARCH_FEAT_SM101_ALL))
#define TCGEN_OK 1
#else
#define TCGEN_OK 0
#endif

// ------------------------- device scratch -----------------------------------
__device__ float g_wdr[(size_t)HIDDEN * INTER];    // 224 MB rounded w_down
__device__ float g_h2[(size_t)TOKENS * INTER];     // 224 MB intermediate
__device__ float g_outb[(size_t)TOKENS * HIDDEN];  //  64 MB split-K partial

// ------------------------- PTX helpers --------------------------------------
__device__ __forceinline__ uint32_t smem_u32(const void* p) {
    uint32_t a;
    asm("{ .reg .u64 t; cvta.to.shared.u64 t, %1; cvt.u32.u64 %0, t; }"
        : "=r"(a) : "l"(p));
    return a;
}

#if TCGEN_OK
__device__ __forceinline__ uint32_t ctarank() {
    uint32_t r;
    asm("mov.u32 %0, %%cluster_ctarank;" : "=r"(r));
    return r;
}
__device__ __forceinline__ void mbar_init(uint32_t a, uint32_t c) {
    asm volatile("mbarrier.init.shared.b64 [%0], %1;" :: "r"(a), "r"(c) : "memory");
}
__device__ __forceinline__ void mbar_expect_tx(uint32_t a, uint32_t bytes) {
    asm volatile("mbarrier.arrive.expect_tx.shared.b64 _, [%0], %1;"
                 :: "r"(a), "r"(bytes) : "memory");
}
__device__ __forceinline__ void mbar_arrive_leader(uint32_t a) {
    asm volatile(
        "{\n\t.reg .b32 r;\n\t"
        "and.b32 r, %0, 0xFEFFFFFF;\n\t"
        "mbarrier.arrive.shared::cluster.b64 _, [r];\n\t}"
        :: "r"(a) : "memory");
}
__device__ __forceinline__ void mbar_wait(uint32_t a, uint32_t parity) {
    asm volatile(
        "{\n\t"
        ".reg .pred P;\n"
        "LAB_%=:\n\t"
        "mbarrier.try_wait.parity.acquire.cta.shared::cta.b64 P, [%0], %1, 0x989680;\n\t"
        "@P bra DONE_%=;\n\t"
        "bra LAB_%=;\n"
        "DONE_%=:\n\t"
        "}"
        :: "r"(a), "r"(parity) : "memory");
}
__device__ __forceinline__ void tcg_commit_mc2(uint32_t a) {
    asm volatile(
        "tcgen05.commit.cta_group::2.mbarrier::arrive::one.shared::cluster."
        "multicast::cluster.b64 [%0], %1;"
        :: "r"(a), "h"((uint16_t)0x3) : "memory");
}
__device__ __forceinline__ void tma2d_cg2(uint32_t dst, const CUtensorMap* m,
                                          int cx, int cy, uint32_t bar) {
    asm volatile(
        "{\n\t.reg .b32 lb;\n\t"
        "and.b32 lb, %4, 0xFEFFFFFF;\n\t"
        "cp.async.bulk.tensor.2d.cta_group::2.shared::cluster.global.tile."
        "mbarrier::complete_tx::bytes [%0], [%1, {%2, %3}], [lb];\n\t}"
        :: "r"(dst), "l"(m), "r"(cx), "r"(cy), "r"(bar) : "memory");
}
#define TC_ALLOC_CG2(dstsmem, n) \
    asm volatile("tcgen05.alloc.cta_group::2.sync.aligned.shared::cta.b32 [%0], %1;" \
                 :: "r"(dstsmem), "r"(n) : "memory")
#define TC_DEALLOC_CG2(t, n) \
    asm volatile("tcgen05.dealloc.cta_group::2.sync.aligned.b32 %0, %1;" :: "r"(t), "r"(n))
#define TC_RELINQ_CG2() \
    asm volatile("tcgen05.relinquish_alloc_permit.cta_group::2.sync.aligned;")
#define TC_FENCE_AFTER()  asm volatile("tcgen05.fence::after_thread_sync;" ::: "memory")
#define TC_FENCE_BEFORE() asm volatile("tcgen05.fence::before_thread_sync;" ::: "memory")
#define TC_WAIT_LD()      asm volatile("tcgen05.wait::ld.sync.aligned;" ::: "memory")
#define CLUSTER_ARRIVE()  asm volatile("barrier.cluster.arrive.aligned;" ::: "memory")
#define CLUSTER_WAIT()    asm volatile("barrier.cluster.wait.aligned;" ::: "memory")

__device__ __forceinline__ void mma_tf32_ss_cg2(uint32_t d_tmem, uint64_t ad, uint64_t bd,
                                                uint32_t idesc, uint32_t en) {
    asm volatile(
        "{\n\t"
        ".reg .pred p;\n\t"
        "setp.ne.u32 p, %5, 0;\n\t"
        "tcgen05.mma.cta_group::2.kind::tf32 [%0], %1, %2, %3, "
        "{%4, %4, %4, %4, %4, %4, %4, %4}, p;\n\t"
        "}"
        :: "r"(d_tmem), "l"(ad), "l"(bd), "r"(idesc), "r"(0u), "r"(en) : "memory");
}

__device__ __forceinline__ uint64_t make_desc(uint32_t addr) {
    return ((uint64_t)2 << 61) | ((uint64_t)1 << 46) | ((uint64_t)64 << 32) |
           ((uint64_t)1 << 16) | ((uint64_t)(addr >> 4) & 0x3FFF);
}

__device__ __forceinline__ void ldtm32(uint32_t* r, uint32_t addr) {
    asm volatile(
        "tcgen05.ld.sync.aligned.32x32b.x32.b32 "
        "{%0, %1, %2, %3, %4, %5, %6, %7, "
        " %8, %9, %10, %11, %12, %13, %14, %15, "
        " %16, %17, %18, %19, %20, %21, %22, %23, "
        " %24, %25, %26, %27, %28, %29, %30, %31}, [%32];"
        : "=r"(r[0]),  "=r"(r[1]),  "=r"(r[2]),  "=r"(r[3]),
          "=r"(r[4]),  "=r"(r[5]),  "=r"(r[6]),  "=r"(r[7]),
          "=r"(r[8]),  "=r"(r[9]),  "=r"(r[10]), "=r"(r[11]),
          "=r"(r[12]), "=r"(r[13]), "=r"(r[14]), "=r"(r[15]),
          "=r"(r[16]), "=r"(r[17]), "=r"(r[18]), "=r"(r[19]),
          "=r"(r[20]), "=r"(r[21]), "=r"(r[22]), "=r"(r[23]),
          "=r"(r[24]), "=r"(r[25]), "=r"(r[26]), "=r"(r[27]),
          "=r"(r[28]), "=r"(r[29]), "=r"(r[30]), "=r"(r[31])
        : "r"(addr));
}
#endif  // TCGEN_OK

__device__ __forceinline__ float rna_tf32(float v) {
    uint32_t r;
    asm("cvt.rna.tf32.f32 %0, %1;" : "=r"(r) : "f"(v));
    return __uint_as_float(r);
}
// gate/up carry x AND w_gate_up truncation shrink: compensate each by COMP2,
// then silu(gate)*up, then rna-round for the next tf32 GEMM.
__device__ __forceinline__ float silu_mul_comp(uint32_t gb, uint32_t ub) {
    float g = __uint_as_float(gb) * COMP2;
    float u = __uint_as_float(ub) * COMP2;
    float s = g / (1.0f + __expf(-g));
    return rna_tf32(s * u);
}

__device__ __forceinline__ float4 ldg_nc4(const float4* p) {
    float4 v;
    asm volatile("ld.global.nc.v4.f32 {%0,%1,%2,%3}, [%4];"
                 : "=f"(v.x), "=f"(v.y), "=f"(v.z), "=f"(v.w) : "l"(p));
    return v;
}
__device__ __forceinline__ void stg_cs4(float4* p, float4 v) {
    asm volatile("st.global.cs.v4.f32 [%0], {%1,%2,%3,%4};"
                 :: "l"(p), "f"(v.x), "f"(v.y), "f"(v.z), "f"(v.w) : "memory");
}
__device__ __forceinline__ float4 rna4(float4 v) {
    v.x = rna_tf32(v.x);
    v.y = rna_tf32(v.y);
    v.z = rna_tf32(v.z);
    v.w = rna_tf32(v.w);
    return v;
}

// ---------------- reduce: out += outb (split-K recombine) -------------------
// MLP-4 (2 iterations x 2 streams in flight), nc-path for outb, exactly
// 4 CTAs/SM so there is no partial trailing wave.
__global__ void __launch_bounds__(256)
reduce_add_kernel(float4* __restrict__ out, const float4* __restrict__ b, int n4) {
    const int stride = gridDim.x * blockDim.x;
    int i = blockIdx.x * blockDim.x + threadIdx.x;
    for (; i + stride < n4; i += 2 * stride) {
        float4 x0 = out[i];
        float4 y0 = ldg_nc4(b + i);
        float4 x1 = out[i + stride];
        float4 y1 = ldg_nc4(b + i + stride);
        x0.x += y0.x; x0.y += y0.y; x0.z += y0.z; x0.w += y0.w;
        x1.x += y1.x; x1.y += y1.y; x1.z += y1.z; x1.w += y1.w;
        out[i] = x0;
        out[i + stride] = x1;
    }
    if (i < n4) {
        float4 x = out[i];
        float4 y = ldg_nc4(b + i);
        x.x += y.x; x.y += y.y; x.z += y.z; x.w += y.w;
        out[i] = x;
    }
}

// ------------------------- persistent 2CTA tf32 tcgen05 GEMM ----------------
// Cluster(2): tile M=256 (128 rows/CTA), N=256 (B split N/2=128 rows/CTA).
// FUSED (GEMM1): raw x + raw w_gate_up via TMA (COMP2 in epilogue); rank0's
//   B rows = gate block, rank1's = up block; warps 6-7 stream-round
//   w_down -> g_wdr under GEMM1's spare DRAM bandwidth.
// GEMM2: split-K=2, 512 tickets of 224 K-steps; kh=0 -> out, kh=1 -> g_outb
//   (disjoint buffers, plain stores; recombined by reduce_add_kernel).
#define STAGES      6
#define STAGE_BYTES 32768
#define OFF_FULL    8
#define OFF_EMPTY   (OFF_FULL  + 8 * STAGES)
#define OFF_MMAD    (OFF_EMPTY + 8 * STAGES)
#define OFF_EPID    (OFF_MMAD + 16)
#define OFF_STAGE   1024
#define SMEM_TOTAL  (OFF_STAGE + STAGES * STAGE_BYTES)   /* 197632 */
#define STAGE_TX    65536
#define KSPLIT      (INTER / 2)                           /* 7168 */

static constexpr uint32_t IDESC_CG2 =
    (1u << 4) | (2u << 7) | (2u << 10) | ((256u / 8) << 17) | ((256u / 16) << 24);

template <bool FUSED>
__global__ void __launch_bounds__(256, 1) __cluster_dims__(2, 1, 1)
gemm_tf32_kernel(const __grid_constant__ CUtensorMap tma_a,
                 const __grid_constant__ CUtensorMap tma_b,
                 float* __restrict__ out,
                 float* __restrict__ outb,          // GEMM2 kh=1 buffer
                 const float4* __restrict__ rsrc,   // raw w_down (FUSED only)
                 float4* __restrict__ rdst,         // g_wdr      (FUSED only)
                 int rn4) {
#if TCGEN_OK
    constexpr int MB_TILES = 16;                            // 4096 / 256
    constexpr int NK    = FUSED ? (HIDDEN / 32) : (KSPLIT / 32);  // 128 / 224
    constexpr int TOTAL = FUSED ? 1792 : 512;               // tiles / tickets

    extern __shared__ char smem[];
    const uint32_t sb = smem_u32(smem);
    const int tid  = threadIdx.x;
    const int wid  = tid >> 5;
    const int lane = tid & 31;
    const uint32_t rank = ctarank();
    const int cid  = blockIdx.x >> 1;
    const int ncl  = gridDim.x >> 1;
    const int my_tiles = (TOTAL - cid + ncl - 1) / ncl;

    if (tid == 0) {
#pragma unroll
        for (int s = 0; s < STAGES; s++) {
            mbar_init(sb + OFF_FULL  + s * 8, 1);
            mbar_init(sb + OFF_EMPTY + s * 8, 1);
        }
        mbar_init(sb + OFF_MMAD,     1);
        mbar_init(sb + OFF_MMAD + 8, 1);
        mbar_init(sb + OFF_EPID,     256);
        mbar_init(sb + OFF_EPID + 8, 256);
    }
    __syncthreads();
    if (wid == 0) TC_ALLOC_CG2(sb, 512);
    __syncthreads();
    uint32_t tmem;
    asm volatile("ld.shared.b32 %0, [%1];" : "=r"(tmem) : "r"(sb));

    CLUSTER_ARRIVE();
    CLUSTER_WAIT();

    if (wid == 4 && lane == 0) {
        // ---------------- TMA producer (both CTAs) --------------------------
        int st = 0, sph = 1;
        for (int i = 0; i < my_tiles; i++) {
            const int t  = cid + i * ncl;
            const int r_ = FUSED ? t : (t & 255);
            const int mb = r_ % MB_TILES;
            const int nb = r_ / MB_TILES;
            const int kc0 = FUSED ? 0 : ((t >> 8) * KSPLIT);
            const int a_row = mb * 256 + (int)rank * 128;
            const int b_row = FUSED ? (nb * 128 + (int)rank * INTER)
                                    : (nb * 256 + (int)rank * 128);
            for (int ks = 0; ks < NK; ks++) {
                mbar_wait(sb + OFF_EMPTY + st * 8, (uint32_t)sph);
                const uint32_t bar = sb + OFF_FULL + st * 8;
                if (rank == 0) mbar_expect_tx(bar, STAGE_TX);
                const int kc = kc0 + ks * 32;
                const uint32_t base = sb + OFF_STAGE + st * STAGE_BYTES;
                tma2d_cg2(base,         &tma_a, kc, a_row, bar);
                tma2d_cg2(base + 16384, &tma_b, kc, b_row, bar);
                if (++st == STAGES) { st = 0; sph ^= 1; }
            }
        }
    } else if (rank == 0 && wid == 5 && lane == 0) {
        // ---------------- MMA issuer (leader only) --------------------------
        int st = 0, fph = 0;
        int e0 = 1, e1 = 1;
        for (int i = 0; i < my_tiles; i++) {
            const int b = i & 1;
            mbar_wait(sb + OFF_EPID + b * 8, (uint32_t)(b ? e1 : e0));
            if (b) e1 ^= 1; else e0 ^= 1;
            TC_FENCE_AFTER();
            const uint32_t dtm = tmem + b * 256;
            uint32_t en = 0;
            for (int ks = 0; ks < NK; ks++) {
                mbar_wait(sb + OFF_FULL + st * 8, (uint32_t)fph);
                const uint32_t base = sb + OFF_STAGE + st * STAGE_BYTES;
                const uint64_t ad = make_desc(base);
                const uint64_t bd = make_desc(base + 16384);
#pragma unroll
                for (int j = 0; j < 4; j++) {
                    mma_tf32_ss_cg2(dtm, ad + j * 2, bd + j * 2, IDESC_CG2, en);
                    en = 1;
                }
                tcg_commit_mc2(sb + OFF_EMPTY + st * 8);
                if (++st == STAGES) { st = 0; fph ^= 1; }
            }
            tcg_commit_mc2(sb + OFF_MMAD + b * 8);
        }
    } else if (FUSED && wid >= 6) {
        // -------- side crew (FUSED only): stream-round w_down -> g_wdr -----
        const int nthr = gridDim.x * 64;
        for (int i = blockIdx.x * 64 + (tid - 192); i < rn4; i += nthr) {
            stg_cs4(rdst + i, rna4(ldg_nc4(rsrc + i)));
        }
    } else if (tid < 128) {
        // ---------------- epilogue (both CTAs, own 128 rows) -----------------
        int m0 = 0, m1 = 0;
        for (int i = 0; i < my_tiles; i++) {
            const int t  = cid + i * ncl;
            const int r_ = FUSED ? t : (t & 255);
            const int mb = r_ % MB_TILES;
            const int nb = r_ / MB_TILES;
            const int b  = i & 1;
            mbar_wait(sb + OFF_MMAD + b * 8, (uint32_t)(b ? m1 : m0));
            if (b) m1 ^= 1; else m0 ^= 1;
            TC_FENCE_AFTER();
            const uint32_t buf = tmem + b * 256;
            const int row = mb * 256 + (int)rank * 128 + tid;
            if (FUSED) {
                float* dst = out + (size_t)row * INTER + (size_t)nb * 128;
#pragma unroll
                for (int c0 = 0; c0 < 128; c0 += 32) {
                    uint32_t ga[32], ua[32];
                    ldtm32(ga, buf + c0);          // gate: D cols 0-127
                    ldtm32(ua, buf + 128 + c0);    // up:   D cols 128-255
                    TC_WAIT_LD();
#pragma unroll
                    for (int q = 0; q < 8; q++) {
                        float4 v;
                        v.x = silu_mul_comp(ga[q * 4 + 0], ua[q * 4 + 0]);
                        v.y = silu_mul_comp(ga[q * 4 + 1], ua[q * 4 + 1]);
                        v.z = silu_mul_comp(ga[q * 4 + 2], ua[q * 4 + 2]);
                        v.w = silu_mul_comp(ga[q * 4 + 3], ua[q * 4 + 3]);
                        *reinterpret_cast<float4*>(dst + c0 + q * 4) = v;
                    }
                }
            } else {
                float* base = (t >> 8) ? outb : out;    // split-K half select
                float* dst = base + (size_t)row * HIDDEN + (size_t)nb * 256;
#pragma unroll
                for (int c0 = 0; c0 < 256; c0 += 32) {
                    uint32_t da[32];
                    ldtm32(da, buf + c0);
                    TC_WAIT_LD();
#pragma unroll
                    for (int q = 0; q < 8; q++) {
                        float4 v;   // h2 and w_down both rna-rounded: no COMP
                        v.x = __uint_as_float(da[q * 4 + 0]);
                        v.y = __uint_as_float(da[q * 4 + 1]);
                        v.z = __uint_as_float(da[q * 4 + 2]);
                        v.w = __uint_as_float(da[q * 4 + 3]);
                        *reinterpret_cast<float4*>(dst + c0 + q * 4) = v;
                    }
                }
            }
            TC_FENCE_BEFORE();
            mbar_arrive_leader(sb + OFF_EPID + b * 8);
        }
    }
    __syncthreads();
    CLUSTER_ARRIVE();
    CLUSTER_WAIT();
    if (wid == 0) {
        TC_RELINQ_CG2();
        TC_DEALLOC_CG2(tmem, 512);
    }
    CLUSTER_ARRIVE();
    CLUSTER_WAIT();
#endif  // TCGEN_OK
}

// ------------------------- host side ----------------------------------------
typedef CUresult (*PFN_encode)(CUtensorMap*, CUtensorMapDataType, cuuint32_t, void*,
                               const cuuint64_t*, const cuuint64_t*, const cuuint32_t*,
                               const cuuint32_t*, CUtensorMapInterleave, CUtensorMapSwizzle,
                               CUtensorMapL2promotion, CUtensorMapFloatOOBfill);

static PFN_encode get_encode_fn() {
    static void* fn = nullptr;
    if (!fn) {
        cudaDriverEntryPointQueryResult qr;
#if CUDART_VERSION >= 12050
        cudaGetDriverEntryPointByVersion("cuTensorMapEncodeTiled", &fn, 12000,
                                         cudaEnableDefault, &qr);
#else
        cudaGetDriverEntryPoint("cuTensorMapEncodeTiled", &fn, cudaEnableDefault, &qr);
#endif
    }
    return (PFN_encode)fn;
}

static void make_map(CUtensorMap* tm, void* base, uint64_t d0, uint64_t d1) {
    PFN_encode enc = get_encode_fn();
    cuuint64_t dims[2]    = {d0, d1};
    cuuint64_t strides[1] = {d0 * 4};
    cuuint32_t box[2]     = {32, 128};
    cuuint32_t es[2]      = {1, 1};
    enc(tm, CU_TENSOR_MAP_DATA_TYPE_FLOAT32, 2, base, dims, strides, box, es,
        CU_TENSOR_MAP_INTERLEAVE_NONE, CU_TENSOR_MAP_SWIZZLE_128B,
        CU_TENSOR_MAP_L2_PROMOTION_L2_128B, CU_TENSOR_MAP_FLOAT_OOB_FILL_NONE);
}

extern "C" void kernel_launch(void* const* d_in, const int* in_sizes, int n_in,
                              void* d_out, int out_size) {
    const float* x   = (const float*)d_in[0];
    const float* wgu = (const float*)d_in[1];
    const float* wd  = (const float*)d_in[2];
    float* out = (float*)d_out;

    float *p_wdr, *p_h2, *p_outb;
    cudaGetSymbolAddress((void**)&p_wdr,  g_wdr);
    cudaGetSymbolAddress((void**)&p_h2,   g_h2);
    cudaGetSymbolAddress((void**)&p_outb, g_outb);

    CUtensorMap tmA1, tmB1, tmA2, tmB2;
    make_map(&tmA1, (void*)x,    HIDDEN, TOKENS);               // raw x
    make_map(&tmB1, (void*)wgu,  HIDDEN, 2 * (uint64_t)INTER);  // raw weights
    make_map(&tmA2, p_h2,        INTER,  TOKENS);
    make_map(&tmB2, p_wdr,       INTER,  HIDDEN);   // rounded inside GEMM1

    cudaFuncSetAttribute(gemm_tf32_kernel<true>,
                         cudaFuncAttributeMaxDynamicSharedMemorySize, SMEM_TOTAL);
    cudaFuncSetAttribute(gemm_tf32_kernel<false>,
                         cudaFuncAttributeMaxDynamicSharedMemorySize, SMEM_TOTAL);

    int dev = 0;
    cudaGetDevice(&dev);
    int nsm = 148;
    cudaDeviceGetAttribute(&nsm, cudaDevAttrMultiProcessorCount, dev);
    nsm &= ~1;   // multiple of cluster size (2)

    // No prep kernel: x and wgu go in raw (COMP2 in GEMM1 epilogue);
    // wd is rounded by GEMM1's side warps; h2 is rna-rounded at source.

    // GEMM1: h2 = silu(x@Wg^T) * (x@Wu^T), persistent 2CTA clusters.
    // Warps 6-7 stream-round w_down -> g_wdr in the background.
    gemm_tf32_kernel<true><<<nsm, 256, SMEM_TOTAL>>>(
        tmA1, tmB1, p_h2, nullptr, (const float4*)wd, (float4*)p_wdr,
        (int)((size_t)HIDDEN * INTER / 4));

    // GEMM2: out = h2 @ Wd^T, split-K=2 (512 tickets), dual buffers
    gemm_tf32_kernel<false><<<nsm, 192, SMEM_TOTAL>>>(
        tmA2, tmB2, out, p_outb, nullptr, nullptr, 0);

    // recombine split-K halves: out += outb (4 CTAs/SM, no partial wave)
    reduce_add_kernel<<<4 * nsm, 256>>>((float4*)out, (const float4*)p_outb,
                                        TOKENS * HIDDEN / 4);
}

// round 17
// speedup vs baseline: 1.0220x; 1.0058x over previous
#include <cuda_runtime.h>
#include <cuda.h>
#include <cstdint>

#define TOKENS 4096
#define HIDDEN 4096
#define INTER  14336

// tf32 truncation-bias compensation: HW fp32->tf32 truncates mantissa toward
// zero; mean relative shrink per operand ~= 3.4e-4, coherent with the output.
// GEMM1 feeds BOTH operands raw (x and w_gate_up) -> compensate twice.
#define COMP2 1.00068f

#if defined(__CUDA_ARCH__) && (defined(__CUDA_ARCH_FEAT_SM103_ALL) || \
                               defined(__CUDA_ARCH_FEAT_SM100_ALL) || \
                               defined(__CUDA_ARCH_FEAT_SM101_ALL))
#define TCGEN_OK 1
#else
#define TCGEN_OK 0
#endif

// ------------------------- device scratch -----------------------------------
__device__ float g_wdr[(size_t)HIDDEN * INTER];    // 224 MB rounded w_down
__device__ float g_h2[(size_t)TOKENS * INTER];     // 224 MB intermediate
__device__ float g_outb[(size_t)TOKENS * HIDDEN];  //  64 MB split-K partial

// ------------------------- PTX helpers --------------------------------------
__device__ __forceinline__ uint32_t smem_u32(const void* p) {
    uint32_t a;
    asm("{ .reg .u64 t; cvta.to.shared.u64 t, %1; cvt.u32.u64 %0, t; }"
        : "=r"(a) : "l"(p));
    return a;
}

#if TCGEN_OK
__device__ __forceinline__ uint32_t ctarank() {
    uint32_t r;
    asm("mov.u32 %0, %%cluster_ctarank;" : "=r"(r));
    return r;
}
__device__ __forceinline__ void mbar_init(uint32_t a, uint32_t c) {
    asm volatile("mbarrier.init.shared.b64 [%0], %1;" :: "r"(a), "r"(c) : "memory");
}
__device__ __forceinline__ void mbar_expect_tx(uint32_t a, uint32_t bytes) {
    asm volatile("mbarrier.arrive.expect_tx.shared.b64 _, [%0], %1;"
                 :: "r"(a), "r"(bytes) : "memory");
}
__device__ __forceinline__ void mbar_arrive_leader(uint32_t a) {
    asm volatile(
        "{\n\t.reg .b32 r;\n\t"
        "and.b32 r, %0, 0xFEFFFFFF;\n\t"
        "mbarrier.arrive.shared::cluster.b64 _, [r];\n\t}"
        :: "r"(a) : "memory");
}
__device__ __forceinline__ void mbar_wait(uint32_t a, uint32_t parity) {
    asm volatile(
        "{\n\t"
        ".reg .pred P;\n"
        "LAB_%=:\n\t"
        "mbarrier.try_wait.parity.acquire.cta.shared::cta.b64 P, [%0], %1, 0x989680;\n\t"
        "@P bra DONE_%=;\n\t"
        "bra LAB_%=;\n"
        "DONE_%=:\n\t"
        "}"
        :: "r"(a), "r"(parity) : "memory");
}
__device__ __forceinline__ void tcg_commit_mc2(uint32_t a) {
    asm volatile(
        "tcgen05.commit.cta_group::2.mbarrier::arrive::one.shared::cluster."
        "multicast::cluster.b64 [%0], %1;"
        :: "r"(a), "h"((uint16_t)0x3) : "memory");
}
__device__ __forceinline__ void tma2d_cg2(uint32_t dst, const CUtensorMap* m,
                                          int cx, int cy, uint32_t bar) {
    asm volatile(
        "{\n\t.reg .b32 lb;\n\t"
        "and.b32 lb, %4, 0xFEFFFFFF;\n\t"
        "cp.async.bulk.tensor.2d.cta_group::2.shared::cluster.global.tile."
        "mbarrier::complete_tx::bytes [%0], [%1, {%2, %3}], [lb];\n\t}"
        :: "r"(dst), "l"(m), "r"(cx), "r"(cy), "r"(bar) : "memory");
}
#define TC_ALLOC_CG2(dstsmem, n) \
    asm volatile("tcgen05.alloc.cta_group::2.sync.aligned.shared::cta.b32 [%0], %1;" \
                 :: "r"(dstsmem), "r"(n) : "memory")
#define TC_DEALLOC_CG2(t, n) \
    asm volatile("tcgen05.dealloc.cta_group::2.sync.aligned.b32 %0, %1;" :: "r"(t), "r"(n))
#define TC_RELINQ_CG2() \
    asm volatile("tcgen05.relinquish_alloc_permit.cta_group::2.sync.aligned;")
#define TC_FENCE_AFTER()  asm volatile("tcgen05.fence::after_thread_sync;" ::: "memory")
#define TC_FENCE_BEFORE() asm volatile("tcgen05.fence::before_thread_sync;" ::: "memory")
#define TC_WAIT_LD()      asm volatile("tcgen05.wait::ld.sync.aligned;" ::: "memory")
#define CLUSTER_ARRIVE()  asm volatile("barrier.cluster.arrive.aligned;" ::: "memory")
#define CLUSTER_WAIT()    asm volatile("barrier.cluster.wait.aligned;" ::: "memory")

__device__ __forceinline__ void mma_tf32_ss_cg2(uint32_t d_tmem, uint64_t ad, uint64_t bd,
                                                uint32_t idesc, uint32_t en) {
    asm volatile(
        "{\n\t"
        ".reg .pred p;\n\t"
        "setp.ne.u32 p, %5, 0;\n\t"
        "tcgen05.mma.cta_group::2.kind::tf32 [%0], %1, %2, %3, "
        "{%4, %4, %4, %4, %4, %4, %4, %4}, p;\n\t"
        "}"
        :: "r"(d_tmem), "l"(ad), "l"(bd), "r"(idesc), "r"(0u), "r"(en) : "memory");
}

__device__ __forceinline__ uint64_t make_desc(uint32_t addr) {
    return ((uint64_t)2 << 61) | ((uint64_t)1 << 46) | ((uint64_t)64 << 32) |
           ((uint64_t)1 << 16) | ((uint64_t)(addr >> 4) & 0x3FFF);
}

__device__ __forceinline__ void ldtm32(uint32_t* r, uint32_t addr) {
    asm volatile(
        "tcgen05.ld.sync.aligned.32x32b.x32.b32 "
        "{%0, %1, %2, %3, %4, %5, %6, %7, "
        " %8, %9, %10, %11, %12, %13, %14, %15, "
        " %16, %17, %18, %19, %20, %21, %22, %23, "
        " %24, %25, %26, %27, %28, %29, %30, %31}, [%32];"
        : "=r"(r[0]),  "=r"(r[1]),  "=r"(r[2]),  "=r"(r[3]),
          "=r"(r[4]),  "=r"(r[5]),  "=r"(r[6]),  "=r"(r[7]),
          "=r"(r[8]),  "=r"(r[9]),  "=r"(r[10]), "=r"(r[11]),
          "=r"(r[12]), "=r"(r[13]), "=r"(r[14]), "=r"(r[15]),
          "=r"(r[16]), "=r"(r[17]), "=r"(r[18]), "=r"(r[19]),
          "=r"(r[20]), "=r"(r[21]), "=r"(r[22]), "=r"(r[23]),
          "=r"(r[24]), "=r"(r[25]), "=r"(r[26]), "=r"(r[27]),
          "=r"(r[28]), "=r"(r[29]), "=r"(r[30]), "=r"(r[31])
        : "r"(addr));
}
#endif  // TCGEN_OK

__device__ __forceinline__ float rna_tf32(float v) {
    uint32_t r;
    asm("cvt.rna.tf32.f32 %0, %1;" : "=r"(r) : "f"(v));
    return __uint_as_float(r);
}
// gate/up carry x AND w_gate_up truncation shrink: compensate each by COMP2,
// then silu(gate)*up, then rna-round for the next tf32 GEMM.
__device__ __forceinline__ float silu_mul_comp(uint32_t gb, uint32_t ub) {
    float g = __uint_as_float(gb) * COMP2;
    float u = __uint_as_float(ub) * COMP2;
    float s = g / (1.0f + __expf(-g));
    return rna_tf32(s * u);
}

__device__ __forceinline__ float4 ldg_nc4(const float4* p) {
    float4 v;
    asm volatile("ld.global.nc.v4.f32 {%0,%1,%2,%3}, [%4];"
                 : "=f"(v.x), "=f"(v.y), "=f"(v.z), "=f"(v.w) : "l"(p));
    return v;
}
// evict-first streaming store: output data has no reuse before eviction, so
// keep it out of the L2 working set (which holds the 16x-reused B strips).
__device__ __forceinline__ void stg_cs4(float4* p, float4 v) {
    asm volatile("st.global.cs.v4.f32 [%0], {%1,%2,%3,%4};"
                 :: "l"(p), "f"(v.x), "f"(v.y), "f"(v.z), "f"(v.w) : "memory");
}
__device__ __forceinline__ float4 rna4(float4 v) {
    v.x = rna_tf32(v.x);
    v.y = rna_tf32(v.y);
    v.z = rna_tf32(v.z);
    v.w = rna_tf32(v.w);
    return v;
}

// ---------------- reduce: out += outb (split-K recombine) -------------------
__global__ void __launch_bounds__(256)
reduce_add_kernel(float4* __restrict__ out, const float4* __restrict__ b, int n4) {
    const int stride = gridDim.x * blockDim.x;
    int i = blockIdx.x * blockDim.x + threadIdx.x;
    for (; i + stride < n4; i += 2 * stride) {
        float4 x0 = out[i];
        float4 y0 = ldg_nc4(b + i);
        float4 x1 = out[i + stride];
        float4 y1 = ldg_nc4(b + i + stride);
        x0.x += y0.x; x0.y += y0.y; x0.z += y0.z; x0.w += y0.w;
        x1.x += y1.x; x1.y += y1.y; x1.z += y1.z; x1.w += y1.w;
        out[i] = x0;
        out[i + stride] = x1;
    }
    if (i < n4) {
        float4 x = out[i];
        float4 y = ldg_nc4(b + i);
        x.x += y.x; x.y += y.y; x.z += y.z; x.w += y.w;
        out[i] = x;
    }
}

// ------------------------- persistent 2CTA tf32 tcgen05 GEMM ----------------
// Cluster(2): tile M=256 (128 rows/CTA), N=256 (B split N/2=128 rows/CTA).
// FUSED (GEMM1): raw x + raw w_gate_up via TMA (COMP2 in epilogue); rank0's
//   B rows = gate block, rank1's = up block; warps 6-7 stream-round
//   w_down -> g_wdr under GEMM1's spare DRAM bandwidth.
// GEMM2: split-K=2, 512 tickets of 224 K-steps; kh=0 -> out, kh=1 -> g_outb
//   (disjoint buffers, plain stores; recombined by reduce_add_kernel).
#define STAGES      6
#define STAGE_BYTES 32768
#define OFF_FULL    8
#define OFF_EMPTY   (OFF_FULL  + 8 * STAGES)
#define OFF_MMAD    (OFF_EMPTY + 8 * STAGES)
#define OFF_EPID    (OFF_MMAD + 16)
#define OFF_STAGE   1024
#define SMEM_TOTAL  (OFF_STAGE + STAGES * STAGE_BYTES)   /* 197632 */
#define STAGE_TX    65536
#define KSPLIT      (INTER / 2)                           /* 7168 */

static constexpr uint32_t IDESC_CG2 =
    (1u << 4) | (2u << 7) | (2u << 10) | ((256u / 8) << 17) | ((256u / 16) << 24);

template <bool FUSED>
__global__ void __launch_bounds__(256, 1) __cluster_dims__(2, 1, 1)
gemm_tf32_kernel(const __grid_constant__ CUtensorMap tma_a,
                 const __grid_constant__ CUtensorMap tma_b,
                 float* __restrict__ out,
                 float* __restrict__ outb,          // GEMM2 kh=1 buffer
                 const float4* __restrict__ rsrc,   // raw w_down (FUSED only)
                 float4* __restrict__ rdst,         // g_wdr      (FUSED only)
                 int rn4) {
#if TCGEN_OK
    constexpr int MB_TILES = 16;                            // 4096 / 256
    constexpr int NK    = FUSED ? (HIDDEN / 32) : (KSPLIT / 32);  // 128 / 224
    constexpr int TOTAL = FUSED ? 1792 : 512;               // tiles / tickets

    extern __shared__ char smem[];
    const uint32_t sb = smem_u32(smem);
    const int tid  = threadIdx.x;
    const int wid  = tid >> 5;
    const int lane = tid & 31;
    const uint32_t rank = ctarank();
    const int cid  = blockIdx.x >> 1;
    const int ncl  = gridDim.x >> 1;
    const int my_tiles = (TOTAL - cid + ncl - 1) / ncl;

    if (tid == 0) {
#pragma unroll
        for (int s = 0; s < STAGES; s++) {
            mbar_init(sb + OFF_FULL  + s * 8, 1);
            mbar_init(sb + OFF_EMPTY + s * 8, 1);
        }
        mbar_init(sb + OFF_MMAD,     1);
        mbar_init(sb + OFF_MMAD + 8, 1);
        mbar_init(sb + OFF_EPID,     256);
        mbar_init(sb + OFF_EPID + 8, 256);
    }
    __syncthreads();
    if (wid == 0) TC_ALLOC_CG2(sb, 512);
    __syncthreads();
    uint32_t tmem;
    asm volatile("ld.shared.b32 %0, [%1];" : "=r"(tmem) : "r"(sb));

    CLUSTER_ARRIVE();
    CLUSTER_WAIT();

    if (wid == 4 && lane == 0) {
        // ---------------- TMA producer (both CTAs) --------------------------
        int st = 0, sph = 1;
        for (int i = 0; i < my_tiles; i++) {
            const int t  = cid + i * ncl;
            const int r_ = FUSED ? t : (t & 255);
            const int mb = r_ % MB_TILES;
            const int nb = r_ / MB_TILES;
            const int kc0 = FUSED ? 0 : ((t >> 8) * KSPLIT);
            const int a_row = mb * 256 + (int)rank * 128;
            const int b_row = FUSED ? (nb * 128 + (int)rank * INTER)
                                    : (nb * 256 + (int)rank * 128);
            for (int ks = 0; ks < NK; ks++) {
                mbar_wait(sb + OFF_EMPTY + st * 8, (uint32_t)sph);
                const uint32_t bar = sb + OFF_FULL + st * 8;
                if (rank == 0) mbar_expect_tx(bar, STAGE_TX);
                const int kc = kc0 + ks * 32;
                const uint32_t base = sb + OFF_STAGE + st * STAGE_BYTES;
                tma2d_cg2(base,         &tma_a, kc, a_row, bar);
                tma2d_cg2(base + 16384, &tma_b, kc, b_row, bar);
                if (++st == STAGES) { st = 0; sph ^= 1; }
            }
        }
    } else if (rank == 0 && wid == 5 && lane == 0) {
        // ---------------- MMA issuer (leader only) --------------------------
        int st = 0, fph = 0;
        int e0 = 1, e1 = 1;
        for (int i = 0; i < my_tiles; i++) {
            const int b = i & 1;
            mbar_wait(sb + OFF_EPID + b * 8, (uint32_t)(b ? e1 : e0));
            if (b) e1 ^= 1; else e0 ^= 1;
            TC_FENCE_AFTER();
            const uint32_t dtm = tmem + b * 256;
            uint32_t en = 0;
            for (int ks = 0; ks < NK; ks++) {
                mbar_wait(sb + OFF_FULL + st * 8, (uint32_t)fph);
                const uint32_t base = sb + OFF_STAGE + st * STAGE_BYTES;
                const uint64_t ad = make_desc(base);
                const uint64_t bd = make_desc(base + 16384);
#pragma unroll
                for (int j = 0; j < 4; j++) {
                    mma_tf32_ss_cg2(dtm, ad + j * 2, bd + j * 2, IDESC_CG2, en);
                    en = 1;
                }
                tcg_commit_mc2(sb + OFF_EMPTY + st * 8);
                if (++st == STAGES) { st = 0; fph ^= 1; }
            }
            tcg_commit_mc2(sb + OFF_MMAD + b * 8);
        }
    } else if (FUSED && wid >= 6) {
        // -------- side crew (FUSED only): stream-round w_down -> g_wdr -----
        const int nthr = gridDim.x * 64;
        for (int i = blockIdx.x * 64 + (tid - 192); i < rn4; i += nthr) {
            stg_cs4(rdst + i, rna4(ldg_nc4(rsrc + i)));
        }
    } else if (tid < 128) {
        // ---------------- epilogue (both CTAs, own 128 rows) -----------------
        int m0 = 0, m1 = 0;
        for (int i = 0; i < my_tiles; i++) {
            const int t  = cid + i * ncl;
            const int r_ = FUSED ? t : (t & 255);
            const int mb = r_ % MB_TILES;
            const int nb = r_ / MB_TILES;
            const int b  = i & 1;
            mbar_wait(sb + OFF_MMAD + b * 8, (uint32_t)(b ? m1 : m0));
            if (b) m1 ^= 1; else m0 ^= 1;
            TC_FENCE_AFTER();
            const uint32_t buf = tmem + b * 256;
            const int row = mb * 256 + (int)rank * 128 + tid;
            if (FUSED) {
                float* dst = out + (size_t)row * INTER + (size_t)nb * 128;
#pragma unroll
                for (int c0 = 0; c0 < 128; c0 += 32) {
                    uint32_t ga[32], ua[32];
                    ldtm32(ga, buf + c0);          // gate: D cols 0-127
                    ldtm32(ua, buf + 128 + c0);    // up:   D cols 128-255
                    TC_WAIT_LD();
#pragma unroll
                    for (int q = 0; q < 8; q++) {
                        float4 v;
                        v.x = silu_mul_comp(ga[q * 4 + 0], ua[q * 4 + 0]);
                        v.y = silu_mul_comp(ga[q * 4 + 1], ua[q * 4 + 1]);
                        v.z = silu_mul_comp(ga[q * 4 + 2], ua[q * 4 + 2]);
                        v.w = silu_mul_comp(ga[q * 4 + 3], ua[q * 4 + 3]);
                        stg_cs4(reinterpret_cast<float4*>(dst + c0 + q * 4), v);
                    }
                }
            } else {
                float* base = (t >> 8) ? outb : out;    // split-K half select
                float* dst = base + (size_t)row * HIDDEN + (size_t)nb * 256;
#pragma unroll
                for (int c0 = 0; c0 < 256; c0 += 32) {
                    uint32_t da[32];
                    ldtm32(da, buf + c0);
                    TC_WAIT_LD();
#pragma unroll
                    for (int q = 0; q < 8; q++) {
                        float4 v;   // h2 and w_down both rna-rounded: no COMP
                        v.x = __uint_as_float(da[q * 4 + 0]);
                        v.y = __uint_as_float(da[q * 4 + 1]);
                        v.z = __uint_as_float(da[q * 4 + 2]);
                        v.w = __uint_as_float(da[q * 4 + 3]);
                        stg_cs4(reinterpret_cast<float4*>(dst + c0 + q * 4), v);
                    }
                }
            }
            TC_FENCE_BEFORE();
            mbar_arrive_leader(sb + OFF_EPID + b * 8);
        }
    }
    __syncthreads();
    CLUSTER_ARRIVE();
    CLUSTER_WAIT();
    if (wid == 0) {
        TC_RELINQ_CG2();
        TC_DEALLOC_CG2(tmem, 512);
    }
    CLUSTER_ARRIVE();
    CLUSTER_WAIT();
#endif  // TCGEN_OK
}

// ------------------------- host side ----------------------------------------
typedef CUresult (*PFN_encode)(CUtensorMap*, CUtensorMapDataType, cuuint32_t, void*,
                               const cuuint64_t*, const cuuint64_t*, const cuuint32_t*,
                               const cuuint32_t*, CUtensorMapInterleave, CUtensorMapSwizzle,
                               CUtensorMapL2promotion, CUtensorMapFloatOOBfill);

static PFN_encode get_encode_fn() {
    static void* fn = nullptr;
    if (!fn) {
        cudaDriverEntryPointQueryResult qr;
#if CUDART_VERSION >= 12050
        cudaGetDriverEntryPointByVersion("cuTensorMapEncodeTiled", &fn, 12000,
                                         cudaEnableDefault, &qr);
#else
        cudaGetDriverEntryPoint("cuTensorMapEncodeTiled", &fn, cudaEnableDefault, &qr);
#endif
    }
    return (PFN_encode)fn;
}

static void make_map(CUtensorMap* tm, void* base, uint64_t d0, uint64_t d1) {
    PFN_encode enc = get_encode_fn();
    cuuint64_t dims[2]    = {d0, d1};
    cuuint64_t strides[1] = {d0 * 4};
    cuuint32_t box[2]     = {32, 128};
    cuuint32_t es[2]      = {1, 1};
    enc(tm, CU_TENSOR_MAP_DATA_TYPE_FLOAT32, 2, base, dims, strides, box, es,
        CU_TENSOR_MAP_INTERLEAVE_NONE, CU_TENSOR_MAP_SWIZZLE_128B,
        CU_TENSOR_MAP_L2_PROMOTION_L2_256B, CU_TENSOR_MAP_FLOAT_OOB_FILL_NONE);
}

extern "C" void kernel_launch(void* const* d_in, const int* in_sizes, int n_in,
                              void* d_out, int out_size) {
    const float* x   = (const float*)d_in[0];
    const float* wgu = (const float*)d_in[1];
    const float* wd  = (const float*)d_in[2];
    float* out = (float*)d_out;

    float *p_wdr, *p_h2, *p_outb;
    cudaGetSymbolAddress((void**)&p_wdr,  g_wdr);
    cudaGetSymbolAddress((void**)&p_h2,   g_h2);
    cudaGetSymbolAddress((void**)&p_outb, g_outb);

    CUtensorMap tmA1, tmB1, tmA2, tmB2;
    make_map(&tmA1, (void*)x,    HIDDEN, TOKENS);               // raw x
    make_map(&tmB1, (void*)wgu,  HIDDEN, 2 * (uint64_t)INTER);  // raw weights
    make_map(&tmA2, p_h2,        INTER,  TOKENS);
    make_map(&tmB2, p_wdr,       INTER,  HIDDEN);   // rounded inside GEMM1

    cudaFuncSetAttribute(gemm_tf32_kernel<true>,
                         cudaFuncAttributeMaxDynamicSharedMemorySize, SMEM_TOTAL);
    cudaFuncSetAttribute(gemm_tf32_kernel<false>,
                         cudaFuncAttributeMaxDynamicSharedMemorySize, SMEM_TOTAL);

    int dev = 0;
    cudaGetDevice(&dev);
    int nsm = 148;
    cudaDeviceGetAttribute(&nsm, cudaDevAttrMultiProcessorCount, dev);
    nsm &= ~1;   // multiple of cluster size (2)

    // No prep kernel: x and wgu go in raw (COMP2 in GEMM1 epilogue);
    // wd is rounded by GEMM1's side warps; h2 is rna-rounded at source.

    // GEMM1: h2 = silu(x@Wg^T) * (x@Wu^T), persistent 2CTA clusters.
    // Warps 6-7 stream-round w_down -> g_wdr in the background.
    gemm_tf32_kernel<true><<<nsm, 256, SMEM_TOTAL>>>(
        tmA1, tmB1, p_h2, nullptr, (const float4*)wd, (float4*)p_wdr,
        (int)((size_t)HIDDEN * INTER / 4));

    // GEMM2: out = h2 @ Wd^T, split-K=2 (512 tickets), dual buffers
    gemm_tf32_kernel<false><<<nsm, 192, SMEM_TOTAL>>>(
        tmA2, tmB2, out, p_outb, nullptr, nullptr, 0);

    // recombine split-K halves: out += outb
    reduce_add_kernel<<<4 * nsm, 256>>>((float4*)out, (const float4*)p_outb,
                                        TOKENS * HIDDEN / 4);
}